// round 9
// baseline (speedup 1.0000x reference)
#include <cuda_runtime.h>
#include <math.h>
#include <stdint.h>

#define B_ 1024
#define T_ 128
#define F_ 32
#define E_ 16
#define H_ 20
#define G_ 80      // 4*H
#define D_ 4096    // T*F
#define BT_ (B_ * T_)   // 131072

typedef unsigned long long ull;

// scratch (__device__ globals; no allocations allowed)
__device__ float g_fc1[B_ * D_];                    // relu(x_flat @ fc1_w + b)
__device__ float g_zx[(size_t)E_ * BT_ * G_];       // per-block-private zx slabs
__device__ float g_eo[E_ * B_];                     // per-expert outputs

// ---------------- helpers -------------------------------------------------
__device__ __forceinline__ ull pack2(float lo, float hi) {
    ull r; asm("mov.b64 %0,{%1,%2};" : "=l"(r) : "f"(lo), "f"(hi)); return r;
}
__device__ __forceinline__ float2 unpack2(ull p) {
    float2 v; asm("mov.b64 {%0,%1},%2;" : "=f"(v.x), "=f"(v.y) : "l"(p)); return v;
}
__device__ __forceinline__ void ffma2(ull& d, ull a, ull b) {
    asm("fma.rn.f32x2 %0,%1,%2,%0;" : "+l"(d) : "l"(a), "l"(b));
}
__device__ __forceinline__ float sigmoidf_(float x) {
    return 1.0f / (1.0f + __expf(-x));
}
__device__ __forceinline__ uint32_t f2tf32(float x) {
    uint32_t r; asm("cvt.rna.tf32.f32 %0, %1;" : "=r"(r) : "f"(x)); return r;
}
// D += A(tf32) * B(tf32), m16n8k8
__device__ __forceinline__ void mma_tf32(float* c, const uint32_t* a, const uint32_t* b) {
    asm("mma.sync.aligned.m16n8k8.row.col.f32.tf32.tf32.f32 "
        "{%0,%1,%2,%3},{%4,%5,%6,%7},{%8,%9},{%0,%1,%2,%3};"
        : "+f"(c[0]), "+f"(c[1]), "+f"(c[2]), "+f"(c[3])
        : "r"(a[0]), "r"(a[1]), "r"(a[2]), "r"(a[3]), "r"(b[0]), "r"(b[1]));
}

// ===========================================================================
// kFat: fc1 tf32 GEMM (blocks [0,512)) + self-contained LSTM (blocks [512,1536))
// ===========================================================================
#define FC1_BLOCKS 512
#define LROWS 16
#define LSTM_BLOCKS (E_ * B_ / LROWS)   // 1024

struct SFC {                        // fc1 tile buffers (~29.7 KB)
    uint32_t Ah[128][20];
    uint32_t Al[128][20];
    uint32_t Bh[16][72];
    uint32_t Bl[16][72];
};
struct SZP {                        // zx-prologue buffers (~16.3 KB)
    float bns[F_], bnh[F_];
    float xs[LROWS][8][F_];         // 16 rows x 8 timesteps x 32 features
};
struct SPL {                        // recurrence buffers (~18.4 KB)
    float h1[LROWS][24];            // [0..19] live
    float h2[LROWS][24];
    float z1[LROWS][G_];
    float z2[LROWS][G_];
    float zxb[LROWS][G_];           // staged zx(t)
};
union __align__(16) UA { SFC f; SZP zp; SPL p; };

__global__ void __launch_bounds__(320, 2) kFat(
    const float* __restrict__ x, const float* __restrict__ fc1_w,
    const float* __restrict__ fc1_b,
    const float* __restrict__ bn_gamma, const float* __restrict__ bn_beta,
    const float* __restrict__ bn_mean,  const float* __restrict__ bn_var,
    const float* __restrict__ k1, const float* __restrict__ r1,
    const float* __restrict__ b1,
    const float* __restrict__ k2, const float* __restrict__ r2,
    const float* __restrict__ b2,
    const float* __restrict__ dw, const float* __restrict__ db)
{
    __shared__ UA u;
    const int tid = threadIdx.x;

    if (blockIdx.x < FC1_BLOCKS) {
        // ======== fc1: 128x64 block, mma.sync tf32 hi/lo split (3 passes) ===
        const int m0 = (blockIdx.x >> 6) * 128;
        const int n0 = (blockIdx.x & 63) * 64;
        const bool act = tid < 256;
        const int lane = tid & 31;
        const int wid = tid >> 5;
        const int g  = lane >> 2;
        const int tg = lane & 3;
        const int warp_m = wid & 3;
        const int warp_n = (wid >> 2) & 1;

        const int a_row = tid >> 1;
        const int a_kc  = (tid & 1) * 8;
        const int b_k   = tid >> 4;
        const int b_nc  = (tid & 15) * 4;

        const float* Ap = x + (size_t)(m0 + a_row) * D_ + a_kc;
        const float* Bp = fc1_w + (size_t)b_k * D_ + n0 + b_nc;

        float4 av0, av1, bv;
        if (act) {
            av0 = *(const float4*)Ap;
            av1 = *(const float4*)(Ap + 4);
            bv  = *(const float4*)Bp;
        }

        float c[2][4][4];
        #pragma unroll
        for (int mt = 0; mt < 2; mt++)
            #pragma unroll
            for (int nt = 0; nt < 4; nt++)
                #pragma unroll
                for (int j = 0; j < 4; j++) c[mt][nt][j] = 0.f;

        const int NS = D_ / 16;
        for (int s = 0; s < NS; s++) {
            if (act) {
                float af[8] = {av0.x, av0.y, av0.z, av0.w, av1.x, av1.y, av1.z, av1.w};
                uint32_t hh[8], ll[8];
                #pragma unroll
                for (int j = 0; j < 8; j++) {
                    uint32_t hi = f2tf32(af[j]);
                    float lo = af[j] - __uint_as_float(hi);
                    hh[j] = hi;
                    ll[j] = f2tf32(lo);
                }
                *(uint4*)&u.f.Ah[a_row][a_kc]     = make_uint4(hh[0], hh[1], hh[2], hh[3]);
                *(uint4*)&u.f.Ah[a_row][a_kc + 4] = make_uint4(hh[4], hh[5], hh[6], hh[7]);
                *(uint4*)&u.f.Al[a_row][a_kc]     = make_uint4(ll[0], ll[1], ll[2], ll[3]);
                *(uint4*)&u.f.Al[a_row][a_kc + 4] = make_uint4(ll[4], ll[5], ll[6], ll[7]);
                float bf[4] = {bv.x, bv.y, bv.z, bv.w};
                uint32_t bhh[4], bll[4];
                #pragma unroll
                for (int j = 0; j < 4; j++) {
                    uint32_t hi = f2tf32(bf[j]);
                    float lo = bf[j] - __uint_as_float(hi);
                    bhh[j] = hi;
                    bll[j] = f2tf32(lo);
                }
                *(uint4*)&u.f.Bh[b_k][b_nc] = make_uint4(bhh[0], bhh[1], bhh[2], bhh[3]);
                *(uint4*)&u.f.Bl[b_k][b_nc] = make_uint4(bll[0], bll[1], bll[2], bll[3]);
            }
            __syncthreads();
            if (act && s + 1 < NS) {
                av0 = *(const float4*)(Ap + (size_t)(s + 1) * 16);
                av1 = *(const float4*)(Ap + (size_t)(s + 1) * 16 + 4);
                bv  = *(const float4*)(Bp + (size_t)(s + 1) * 16 * D_);
            }
            if (act && wid < 8) {
                #pragma unroll
                for (int kk = 0; kk < 16; kk += 8) {
                    uint32_t ah[2][4], al[2][4], bh[4][2], bl[4][2];
                    #pragma unroll
                    for (int mt = 0; mt < 2; mt++) {
                        const int ar = warp_m * 32 + mt * 16 + g;
                        ah[mt][0] = u.f.Ah[ar][kk + tg];
                        ah[mt][1] = u.f.Ah[ar + 8][kk + tg];
                        ah[mt][2] = u.f.Ah[ar][kk + tg + 4];
                        ah[mt][3] = u.f.Ah[ar + 8][kk + tg + 4];
                        al[mt][0] = u.f.Al[ar][kk + tg];
                        al[mt][1] = u.f.Al[ar + 8][kk + tg];
                        al[mt][2] = u.f.Al[ar][kk + tg + 4];
                        al[mt][3] = u.f.Al[ar + 8][kk + tg + 4];
                    }
                    #pragma unroll
                    for (int nt = 0; nt < 4; nt++) {
                        const int bc = warp_n * 32 + nt * 8 + g;
                        bh[nt][0] = u.f.Bh[kk + tg][bc];
                        bh[nt][1] = u.f.Bh[kk + tg + 4][bc];
                        bl[nt][0] = u.f.Bl[kk + tg][bc];
                        bl[nt][1] = u.f.Bl[kk + tg + 4][bc];
                    }
                    #pragma unroll
                    for (int mt = 0; mt < 2; mt++)
                        #pragma unroll
                        for (int nt = 0; nt < 4; nt++) {
                            mma_tf32(c[mt][nt], ah[mt], bh[nt]);
                            mma_tf32(c[mt][nt], ah[mt], bl[nt]);
                            mma_tf32(c[mt][nt], al[mt], bh[nt]);
                        }
                }
            }
            __syncthreads();
        }

        if (act && wid < 8) {
            #pragma unroll
            for (int mt = 0; mt < 2; mt++) {
                #pragma unroll
                for (int nt = 0; nt < 4; nt++) {
                    const int row = m0 + warp_m * 32 + mt * 16 + g;
                    const int col = n0 + warp_n * 32 + nt * 8 + 2 * tg;
                    float2 bb = *(const float2*)&fc1_b[col];
                    float2 o0, o1;
                    o0.x = fmaxf(c[mt][nt][0] + bb.x, 0.f);
                    o0.y = fmaxf(c[mt][nt][1] + bb.y, 0.f);
                    o1.x = fmaxf(c[mt][nt][2] + bb.x, 0.f);
                    o1.y = fmaxf(c[mt][nt][3] + bb.y, 0.f);
                    *(float2*)&g_fc1[(size_t)row * D_ + col]       = o0;
                    *(float2*)&g_fc1[(size_t)(row + 8) * D_ + col] = o1;
                }
            }
        }
        return;
    }

    // ============== LSTM block: zx prologue + fused 2-layer recurrence ======
    const int lb = blockIdx.x - FC1_BLOCKS;
    const int e = lb >> 6;                 // 64 blocks per expert
    const int row0 = (lb & 63) * LROWS;

    const int q = tid / G_;                // 0..3 -> rows 4q..4q+3
    const int g = tid - q * G_;            // gate column 0..79

    // ---------- phase 0: zx slab (block-private) ---------------------------
    {
        if (tid < F_) {
            float scv = bn_gamma[tid] * rsqrtf(bn_var[tid] + 1e-3f);
            u.zp.bns[tid] = scv;
            u.zp.bnh[tid] = bn_beta[tid] - bn_mean[tid] * scv;
        }
        // wk1 column g (registers; live range ends before recurrence weights)
        ull w1[16];
        #pragma unroll
        for (int j = 0; j < 16; j++)
            w1[j] = pack2(k1[(e * F_ + 2 * j) * G_ + g],
                          k1[(e * F_ + 2 * j + 1) * G_ + g]);
        const float bias1 = b1[e * G_ + g];
        __syncthreads();                           // bn tables ready

        const size_t base_e = (size_t)e * BT_;
        for (int c = 0; c < 16; c++) {             // 16 chunks of 8 timesteps
            // stage xs[16 rows][8 t][32 f] with BN fused (1024 float4 loads)
            for (int idx = tid; idx < 1024; idx += 320) {
                const int rr = idx >> 6;                    // row 0..15
                const int within = idx & 63;                // float4 within row-chunk
                float4 xv = *(const float4*)(x + (size_t)(row0 + rr) * D_ +
                                             c * 256 + within * 4);
                const int f4 = idx & 7;                     // feature/4
                float4 sc = ((const float4*)u.zp.bns)[f4];
                float4 sh = ((const float4*)u.zp.bnh)[f4];
                xv.x = xv.x * sc.x + sh.x;
                xv.y = xv.y * sc.y + sh.y;
                xv.z = xv.z * sc.z + sh.z;
                xv.w = xv.w * sc.w + sh.w;
                ((float4*)u.zp.xs)[idx] = xv;
            }
            __syncthreads();
            // compute zx for 4 rows x 8 timesteps
            #pragma unroll
            for (int i = 0; i < 4; i++) {
                const int row = 4 * q + i;
                const size_t obase = (base_e + (size_t)(row0 + row) * T_ + c * 8) * G_ + g;
                #pragma unroll
                for (int tt = 0; tt < 8; tt++) {
                    ull a0 = pack2(bias1, 0.f), a1 = 0, a2 = 0, a3 = 0;
                    const ulonglong2* xr = (const ulonglong2*)u.zp.xs[row][tt];
                    #pragma unroll
                    for (int j = 0; j < 8; j++) {
                        ulonglong2 X = xr[j];
                        if (j & 1) { ffma2(a1, X.x, w1[2 * j]); ffma2(a3, X.y, w1[2 * j + 1]); }
                        else       { ffma2(a0, X.x, w1[2 * j]); ffma2(a2, X.y, w1[2 * j + 1]); }
                    }
                    float2 s0 = unpack2(a0), s1 = unpack2(a1);
                    float2 s2 = unpack2(a2), s3 = unpack2(a3);
                    g_zx[obase + (size_t)tt * G_] =
                        ((s0.x + s0.y) + (s1.x + s1.y)) + ((s2.x + s2.y) + (s3.x + s3.y));
                }
            }
            __syncthreads();
        }
    }

    // ---------- phase 1: recurrence ----------------------------------------
    const int crow = tid / H_;             // cell row 0..15 (== staging row)
    const int cu   = tid - crow * H_;      // cell unit 0..19
    const int sc4  = cu * 4;               // staging float4 col

    ull wr1[10], wk2[10], wr2[10];
    #pragma unroll
    for (int j = 0; j < 10; j++) {
        wr1[j] = pack2(r1[(e * H_ + 2 * j) * G_ + g], r1[(e * H_ + 2 * j + 1) * G_ + g]);
        wk2[j] = pack2(k2[(e * H_ + 2 * j) * G_ + g], k2[(e * H_ + 2 * j + 1) * G_ + g]);
        wr2[j] = pack2(r2[(e * H_ + 2 * j) * G_ + g], r2[(e * H_ + 2 * j + 1) * G_ + g]);
    }
    const float bias2 = b2[e * G_ + g];

    for (int idx = tid; idx < 2 * LROWS * 24; idx += 320)
        ((float*)u.p.h1)[idx] = 0.f;       // zero h1+h2 (contiguous)

    const float* pzx = g_zx + ((size_t)e * BT_ + (size_t)(row0 + crow) * T_) * G_ + sc4;
    *(float4*)&u.p.zxb[crow][sc4] = *(const float4*)pzx;          // zx(0)
    float4 zv = *(const float4*)(pzx + G_);                        // prefetch zx(1)
    __syncthreads();

    float c1 = 0.f, c2 = 0.f;

    for (int t = 0; t <= T_; t++) {
        // ---- phase A: both layers' gate pre-activations (4 rows each) ------
        if (t < T_) {                       // L1 time t
            #pragma unroll
            for (int i = 0; i < 4; i++) {
                const int row = 4 * q + i;
                ull a0 = 0, a1 = 0, a2 = 0, a3 = 0;
                const ull* hp = (const ull*)u.p.h1[row];
                #pragma unroll
                for (int j = 0; j < 10; j++) {
                    ull hv = hp[j];
                    if (j & 2) { if (j & 1) ffma2(a3, hv, wr1[j]); else ffma2(a2, hv, wr1[j]); }
                    else       { if (j & 1) ffma2(a1, hv, wr1[j]); else ffma2(a0, hv, wr1[j]); }
                }
                float2 s0 = unpack2(a0), s1 = unpack2(a1);
                float2 s2 = unpack2(a2), s3 = unpack2(a3);
                u.p.z1[row][g] = u.p.zxb[row][g] +
                    (((s0.x + s0.y) + (s1.x + s1.y)) + ((s2.x + s2.y) + (s3.x + s3.y)));
            }
        }
        if (t >= 1) {                       // L2 time t-1
            #pragma unroll
            for (int i = 0; i < 4; i++) {
                const int row = 4 * q + i;
                ull a0 = pack2(bias2, 0.f), a1 = 0, a2 = 0, a3 = 0;
                const ull* h1p = (const ull*)u.p.h1[row];
                const ull* h2p = (const ull*)u.p.h2[row];
                #pragma unroll
                for (int j = 0; j < 10; j++) {
                    ull v1 = h1p[j], v2 = h2p[j];
                    if (j & 1) { ffma2(a1, v1, wk2[j]); ffma2(a3, v2, wr2[j]); }
                    else       { ffma2(a0, v1, wk2[j]); ffma2(a2, v2, wr2[j]); }
                }
                float2 s0 = unpack2(a0), s1 = unpack2(a1);
                float2 s2 = unpack2(a2), s3 = unpack2(a3);
                u.p.z2[row][g] = ((s0.x + s0.y) + (s1.x + s1.y)) +
                                 ((s2.x + s2.y) + (s3.x + s3.y));
            }
        }
        __syncthreads();

        // ---- phase B: one L1 cell + one L2 cell per thread + staging -------
        if (t < T_) {
            float zi = u.p.z1[crow][cu];
            float zf = u.p.z1[crow][H_ + cu];
            float zg = u.p.z1[crow][2 * H_ + cu];
            float zo = u.p.z1[crow][3 * H_ + cu];
            c1 = sigmoidf_(zf) * c1 + sigmoidf_(zi) * fmaxf(zg, 0.f);
            u.p.h1[crow][cu] = sigmoidf_(zo) * fmaxf(c1, 0.f);
        }
        if (t >= 1) {
            float zi = u.p.z2[crow][cu];
            float zf = u.p.z2[crow][H_ + cu];
            float zg = u.p.z2[crow][2 * H_ + cu];
            float zo = u.p.z2[crow][3 * H_ + cu];
            c2 = sigmoidf_(zf) * c2 + sigmoidf_(zi) * fmaxf(zg, 0.f);
            u.p.h2[crow][cu] = sigmoidf_(zo) * fmaxf(c2, 0.f);
        }
        if (t + 1 < T_) {
            *(float4*)&u.p.zxb[crow][sc4] = zv;                    // zx(t+1)
            const int tn = (t + 2 < T_) ? t + 2 : T_ - 1;
            zv = *(const float4*)(pzx + (size_t)tn * G_);
        }
        __syncthreads();
    }

    // dense head: eo[e,b] = h2(T-1) @ dw[e] + db[e]
    if (tid < LROWS) {
        float acc = db[e];
        #pragma unroll
        for (int j = 0; j < H_; j++) acc += u.p.h2[tid][j] * dw[e * H_ + j];
        g_eo[e * B_ + row0 + tid] = acc;
    }
}

// ===========================================================================
// kC: gate (fc1 row @ gate_w, softmax) + combine -> out[b]
// ===========================================================================
__global__ void __launch_bounds__(320) kC_gate_combine(
    const float* __restrict__ GW, const float* __restrict__ GB,
    float* __restrict__ out)
{
    __shared__ float red[10][E_];
    __shared__ float sv[E_];
    __shared__ float ev[E_];
    __shared__ float part[E_];

    const int b = blockIdx.x;
    const int tid = threadIdx.x;
    float acc[E_];
    #pragma unroll
    for (int e = 0; e < E_; e++) acc[e] = 0.f;

    const float* grow = g_fc1 + (size_t)b * D_;
    for (int k = tid; k < D_; k += 320) {
        float gv = grow[k];
        const float4* wp = (const float4*)(GW + (size_t)k * E_);
        float4 w0 = wp[0], w1 = wp[1], w2 = wp[2], w3 = wp[3];
        acc[0]  += gv * w0.x;  acc[1]  += gv * w0.y;
        acc[2]  += gv * w0.z;  acc[3]  += gv * w0.w;
        acc[4]  += gv * w1.x;  acc[5]  += gv * w1.y;
        acc[6]  += gv * w1.z;  acc[7]  += gv * w1.w;
        acc[8]  += gv * w2.x;  acc[9]  += gv * w2.y;
        acc[10] += gv * w2.z;  acc[11] += gv * w2.w;
        acc[12] += gv * w3.x;  acc[13] += gv * w3.y;
        acc[14] += gv * w3.z;  acc[15] += gv * w3.w;
    }
    #pragma unroll
    for (int e = 0; e < E_; e++) {
        #pragma unroll
        for (int off = 16; off > 0; off >>= 1)
            acc[e] += __shfl_down_sync(0xffffffffu, acc[e], off);
    }
    const int warp = tid >> 5, lane = tid & 31;
    if (lane == 0) {
        #pragma unroll
        for (int e = 0; e < E_; e++) red[warp][e] = acc[e];
    }
    __syncthreads();
    if (tid < E_) {
        float s = GB[tid];
        #pragma unroll
        for (int w = 0; w < 10; w++) s += red[w][tid];
        sv[tid] = s;
    }
    __syncthreads();
    if (tid < E_) {
        float m = sv[0];
        #pragma unroll
        for (int e = 1; e < E_; e++) m = fmaxf(m, sv[e]);
        ev[tid] = expf(sv[tid] - m);
    }
    __syncthreads();
    if (tid < E_) {
        float s = 0.f;
        #pragma unroll
        for (int e = 0; e < E_; e++) s += ev[e];
        part[tid] = (ev[tid] / s) * g_eo[tid * B_ + b];
    }
    __syncthreads();
    if (tid == 0) {
        float s = 0.f;
        #pragma unroll
        for (int e = 0; e < E_; e++) s += part[e];
        out[b] = s;
    }
}

// ---------------------------------------------------------------------------
extern "C" void kernel_launch(void* const* d_in, const int* in_sizes, int n_in,
                              void* d_out, int out_size)
{
    const float* x        = (const float*)d_in[0];
    const float* bn_gamma = (const float*)d_in[1];
    const float* bn_beta  = (const float*)d_in[2];
    const float* bn_mean  = (const float*)d_in[3];
    const float* bn_var   = (const float*)d_in[4];
    const float* k1       = (const float*)d_in[5];
    const float* r1       = (const float*)d_in[6];
    const float* b1       = (const float*)d_in[7];
    const float* k2       = (const float*)d_in[8];
    const float* r2       = (const float*)d_in[9];
    const float* b2       = (const float*)d_in[10];
    const float* dw       = (const float*)d_in[11];
    const float* db       = (const float*)d_in[12];
    const float* fc1_w    = (const float*)d_in[13];
    const float* fc1_b    = (const float*)d_in[14];
    const float* gate_w   = (const float*)d_in[15];
    const float* gate_b   = (const float*)d_in[16];
    float* out = (float*)d_out;

    kFat<<<FC1_BLOCKS + LSTM_BLOCKS, 320>>>(
        x, fc1_w, fc1_b, bn_gamma, bn_beta, bn_mean, bn_var,
        k1, r1, b1, k2, r2, b2, dw, db);

    kC_gate_combine<<<B_, 320>>>(gate_w, gate_b, out);
}

// round 10
// speedup vs baseline: 1.1420x; 1.1420x over previous
#include <cuda_runtime.h>
#include <math.h>
#include <stdint.h>

#define B_ 1024
#define T_ 128
#define F_ 32
#define E_ 16
#define H_ 20
#define G_ 80      // 4*H
#define D_ 4096    // T*F

typedef unsigned long long ull;

// scratch (__device__ globals; no allocations allowed)
__device__ float g_fc1[B_ * D_];   // relu(x_flat @ fc1_w + b)
__device__ float g_eo[E_ * B_];    // per-expert outputs

// ---------------- helpers -------------------------------------------------
__device__ __forceinline__ ull pack2(float lo, float hi) {
    ull r; asm("mov.b64 %0,{%1,%2};" : "=l"(r) : "f"(lo), "f"(hi)); return r;
}
__device__ __forceinline__ float2 unpack2(ull p) {
    float2 v; asm("mov.b64 {%0,%1},%2;" : "=f"(v.x), "=f"(v.y) : "l"(p)); return v;
}
__device__ __forceinline__ void ffma2(ull& d, ull a, ull b) {
    asm("fma.rn.f32x2 %0,%1,%2,%0;" : "+l"(d) : "l"(a), "l"(b));
}
__device__ __forceinline__ float sigmoidf_(float x) {
    return 1.0f / (1.0f + __expf(-x));
}
__device__ __forceinline__ uint32_t f2tf32(float x) {
    uint32_t r; asm("cvt.rna.tf32.f32 %0, %1;" : "=r"(r) : "f"(x)); return r;
}
// D += A(tf32) * B(tf32), m16n8k8
__device__ __forceinline__ void mma_tf32(float* c, const uint32_t* a, const uint32_t* b) {
    asm("mma.sync.aligned.m16n8k8.row.col.f32.tf32.tf32.f32 "
        "{%0,%1,%2,%3},{%4,%5,%6,%7},{%8,%9},{%0,%1,%2,%3};"
        : "+f"(c[0]), "+f"(c[1]), "+f"(c[2]), "+f"(c[3])
        : "r"(a[0]), "r"(a[1]), "r"(a[2]), "r"(a[3]), "r"(b[0]), "r"(b[1]));
}

// ===========================================================================
// kFat: fc1 tf32 GEMM (blocks [0,512)) + split-half LSTM (blocks [512,1536))
// ===========================================================================
#define FC1_BLOCKS 512
#define LROWS 16
#define LSTM_BLOCKS (E_ * B_ / LROWS)   // 1024

struct SFC {                        // fc1 tile buffers (~29.7 KB)
    uint32_t Ah[128][20];
    uint32_t Al[128][20];
    uint32_t Bh[16][72];
    uint32_t Bl[16][72];
};
struct SPL {                        // lstm buffers (~14 KB)
    float bns[F_], bnh[F_];
    float xt[LROWS][F_];            // 16 rows x 32 features (BN'd x_t)
    float h1[LROWS][24];            // [0..19] live
    float h2[LROWS][24];
    float z1[LROWS][G_];
    float z2[LROWS][G_];
};
union __align__(16) UA { SFC f; SPL p; };

__global__ void __launch_bounds__(320, 2) kFat(
    const float* __restrict__ x, const float* __restrict__ fc1_w,
    const float* __restrict__ fc1_b,
    const float* __restrict__ bn_gamma, const float* __restrict__ bn_beta,
    const float* __restrict__ bn_mean,  const float* __restrict__ bn_var,
    const float* __restrict__ k1, const float* __restrict__ r1,
    const float* __restrict__ b1,
    const float* __restrict__ k2, const float* __restrict__ r2,
    const float* __restrict__ b2,
    const float* __restrict__ dw, const float* __restrict__ db)
{
    __shared__ UA u;
    const int tid = threadIdx.x;

    if (blockIdx.x < FC1_BLOCKS) {
        // ======== fc1: 128x64 block, mma.sync tf32 hi/lo split (3 passes) ===
        const int m0 = (blockIdx.x >> 6) * 128;
        const int n0 = (blockIdx.x & 63) * 64;
        const bool act = tid < 256;
        const int lane = tid & 31;
        const int wid = tid >> 5;
        const int g  = lane >> 2;
        const int tg = lane & 3;
        const int warp_m = wid & 3;
        const int warp_n = (wid >> 2) & 1;

        const int a_row = tid >> 1;
        const int a_kc  = (tid & 1) * 8;
        const int b_k   = tid >> 4;
        const int b_nc  = (tid & 15) * 4;

        const float* Ap = x + (size_t)(m0 + a_row) * D_ + a_kc;
        const float* Bp = fc1_w + (size_t)b_k * D_ + n0 + b_nc;

        float4 av0, av1, bv;
        if (act) {
            av0 = *(const float4*)Ap;
            av1 = *(const float4*)(Ap + 4);
            bv  = *(const float4*)Bp;
        }

        float c[2][4][4];
        #pragma unroll
        for (int mt = 0; mt < 2; mt++)
            #pragma unroll
            for (int nt = 0; nt < 4; nt++)
                #pragma unroll
                for (int j = 0; j < 4; j++) c[mt][nt][j] = 0.f;

        const int NS = D_ / 16;
        for (int s = 0; s < NS; s++) {
            if (act) {
                float af[8] = {av0.x, av0.y, av0.z, av0.w, av1.x, av1.y, av1.z, av1.w};
                uint32_t hh[8], ll[8];
                #pragma unroll
                for (int j = 0; j < 8; j++) {
                    uint32_t hi = f2tf32(af[j]);
                    float lo = af[j] - __uint_as_float(hi);
                    hh[j] = hi;
                    ll[j] = f2tf32(lo);
                }
                *(uint4*)&u.f.Ah[a_row][a_kc]     = make_uint4(hh[0], hh[1], hh[2], hh[3]);
                *(uint4*)&u.f.Ah[a_row][a_kc + 4] = make_uint4(hh[4], hh[5], hh[6], hh[7]);
                *(uint4*)&u.f.Al[a_row][a_kc]     = make_uint4(ll[0], ll[1], ll[2], ll[3]);
                *(uint4*)&u.f.Al[a_row][a_kc + 4] = make_uint4(ll[4], ll[5], ll[6], ll[7]);
                float bf[4] = {bv.x, bv.y, bv.z, bv.w};
                uint32_t bhh[4], bll[4];
                #pragma unroll
                for (int j = 0; j < 4; j++) {
                    uint32_t hi = f2tf32(bf[j]);
                    float lo = bf[j] - __uint_as_float(hi);
                    bhh[j] = hi;
                    bll[j] = f2tf32(lo);
                }
                *(uint4*)&u.f.Bh[b_k][b_nc] = make_uint4(bhh[0], bhh[1], bhh[2], bhh[3]);
                *(uint4*)&u.f.Bl[b_k][b_nc] = make_uint4(bll[0], bll[1], bll[2], bll[3]);
            }
            __syncthreads();
            if (act && s + 1 < NS) {
                av0 = *(const float4*)(Ap + (size_t)(s + 1) * 16);
                av1 = *(const float4*)(Ap + (size_t)(s + 1) * 16 + 4);
                bv  = *(const float4*)(Bp + (size_t)(s + 1) * 16 * D_);
            }
            if (act && wid < 8) {
                #pragma unroll
                for (int kk = 0; kk < 16; kk += 8) {
                    uint32_t ah[2][4], al[2][4], bh[4][2], bl[4][2];
                    #pragma unroll
                    for (int mt = 0; mt < 2; mt++) {
                        const int ar = warp_m * 32 + mt * 16 + g;
                        ah[mt][0] = u.f.Ah[ar][kk + tg];
                        ah[mt][1] = u.f.Ah[ar + 8][kk + tg];
                        ah[mt][2] = u.f.Ah[ar][kk + tg + 4];
                        ah[mt][3] = u.f.Ah[ar + 8][kk + tg + 4];
                        al[mt][0] = u.f.Al[ar][kk + tg];
                        al[mt][1] = u.f.Al[ar + 8][kk + tg];
                        al[mt][2] = u.f.Al[ar][kk + tg + 4];
                        al[mt][3] = u.f.Al[ar + 8][kk + tg + 4];
                    }
                    #pragma unroll
                    for (int nt = 0; nt < 4; nt++) {
                        const int bc = warp_n * 32 + nt * 8 + g;
                        bh[nt][0] = u.f.Bh[kk + tg][bc];
                        bh[nt][1] = u.f.Bh[kk + tg + 4][bc];
                        bl[nt][0] = u.f.Bl[kk + tg][bc];
                        bl[nt][1] = u.f.Bl[kk + tg + 4][bc];
                    }
                    #pragma unroll
                    for (int mt = 0; mt < 2; mt++)
                        #pragma unroll
                        for (int nt = 0; nt < 4; nt++) {
                            mma_tf32(c[mt][nt], ah[mt], bh[nt]);
                            mma_tf32(c[mt][nt], ah[mt], bl[nt]);
                            mma_tf32(c[mt][nt], al[mt], bh[nt]);
                        }
                }
            }
            __syncthreads();
        }

        if (act && wid < 8) {
            #pragma unroll
            for (int mt = 0; mt < 2; mt++) {
                #pragma unroll
                for (int nt = 0; nt < 4; nt++) {
                    const int row = m0 + warp_m * 32 + mt * 16 + g;
                    const int col = n0 + warp_n * 32 + nt * 8 + 2 * tg;
                    float2 bb = *(const float2*)&fc1_b[col];
                    float2 o0, o1;
                    o0.x = fmaxf(c[mt][nt][0] + bb.x, 0.f);
                    o0.y = fmaxf(c[mt][nt][1] + bb.y, 0.f);
                    o1.x = fmaxf(c[mt][nt][2] + bb.x, 0.f);
                    o1.y = fmaxf(c[mt][nt][3] + bb.y, 0.f);
                    *(float2*)&g_fc1[(size_t)row * D_ + col]       = o0;
                    *(float2*)&g_fc1[(size_t)(row + 8) * D_ + col] = o1;
                }
            }
        }
        return;
    }

    // ============== split-half fused LSTM, 16 rows/block, in-loop x-proj ====
    const int lb = blockIdx.x - FC1_BLOCKS;
    const int e = lb >> 6;                 // 64 blocks per expert
    const int row0 = (lb & 63) * LROWS;

    const bool isL1 = tid < 160;
    const int v = isL1 ? tid : tid - 160;  // 0..159 within half
    const int rp = (v >= 80) ? 1 : 0;      // row group: rows 8rp..8rp+7
    const int g = v - rp * 80;             // gate column 0..79

    // cell mapping: each half's 160 threads own 2 cells: (r,uu), (r,uu+10)
    const int cr = v / 10;                 // cell row 0..15
    const int uu = v - cr * 10;            // 0..9

    // x stagers: 512 slots; all threads take slot tid, tid<192 also slot 320+tid
    const int s1row = tid >> 5,          s1f = tid & 31;
    const bool has2 = tid < 192;
    const int s2row = 10 + (tid >> 5),   s2f = tid & 31;

    // weight columns, packed f32x2 over the K index
    ull wa[16], wb[10];
    float bias;
    if (isL1) {
        #pragma unroll
        for (int j = 0; j < 16; j++)
            wa[j] = pack2(k1[(e * F_ + 2 * j) * G_ + g],
                          k1[(e * F_ + 2 * j + 1) * G_ + g]);
        #pragma unroll
        for (int j = 0; j < 10; j++)
            wb[j] = pack2(r1[(e * H_ + 2 * j) * G_ + g],
                          r1[(e * H_ + 2 * j + 1) * G_ + g]);
        bias = b1[e * G_ + g];
    } else {
        #pragma unroll
        for (int j = 0; j < 10; j++)
            wa[j] = pack2(k2[(e * H_ + 2 * j) * G_ + g],
                          k2[(e * H_ + 2 * j + 1) * G_ + g]);
        #pragma unroll
        for (int j = 0; j < 10; j++)
            wb[j] = pack2(r2[(e * H_ + 2 * j) * G_ + g],
                          r2[(e * H_ + 2 * j + 1) * G_ + g]);
        bias = b2[e * G_ + g];
    }

    if (tid < F_) {
        float scv = bn_gamma[tid] * rsqrtf(bn_var[tid] + 1e-3f);
        u.p.bns[tid] = scv;
        u.p.bnh[tid] = bn_beta[tid] - bn_mean[tid] * scv;
    }
    for (int idx = tid; idx < 2 * LROWS * 24; idx += 320)
        ((float*)u.p.h1)[idx] = 0.f;       // zero h1+h2 (contiguous)
    __syncthreads();                        // bn tables + h zero visible

    const float* px1 = x + (size_t)(row0 + s1row) * D_ + s1f;
    const float* px2 = x + (size_t)(row0 + s2row) * D_ + s2f;
    const float sc1 = u.p.bns[s1f], sh1 = u.p.bnh[s1f];
    const float sc2 = u.p.bns[s2f], sh2 = u.p.bnh[s2f];
    u.p.xt[s1row][s1f] = px1[0] * sc1 + sh1;          // x(0)
    float xv1 = px1[F_];                               // prefetch x(1)
    float xv2 = 0.f;
    if (has2) {
        u.p.xt[s2row][s2f] = px2[0] * sc2 + sh2;
        xv2 = px2[F_];
    }
    __syncthreads();

    float ca = 0.f, cb = 0.f;   // two cell states per thread (this half)

    for (int t = 0; t <= T_; t++) {
        // ---- phase A: gate pre-activations (8 rows per thread) ----
        if (isL1) {
            if (t < T_) {
                #pragma unroll
                for (int i = 0; i < 8; i++) {
                    const int row = 8 * rp + i;
                    ull a0 = pack2(bias, 0.f), a1 = 0, a2 = 0, a3 = 0;
                    const ulonglong2* xr = (const ulonglong2*)u.p.xt[row];
                    #pragma unroll
                    for (int j = 0; j < 8; j++) {
                        ulonglong2 X = xr[j];
                        if (j & 1) { ffma2(a1, X.x, wa[2 * j]); ffma2(a3, X.y, wa[2 * j + 1]); }
                        else       { ffma2(a0, X.x, wa[2 * j]); ffma2(a2, X.y, wa[2 * j + 1]); }
                    }
                    const ull* hp = (const ull*)u.p.h1[row];
                    #pragma unroll
                    for (int j = 0; j < 10; j++) {
                        ull hv = hp[j];
                        if (j & 2) { if (j & 1) ffma2(a3, hv, wb[j]); else ffma2(a2, hv, wb[j]); }
                        else       { if (j & 1) ffma2(a1, hv, wb[j]); else ffma2(a0, hv, wb[j]); }
                    }
                    float2 s0 = unpack2(a0), s1 = unpack2(a1);
                    float2 s2 = unpack2(a2), s3 = unpack2(a3);
                    u.p.z1[row][g] = ((s0.x + s0.y) + (s1.x + s1.y)) +
                                     ((s2.x + s2.y) + (s3.x + s3.y));
                }
            }
        } else {
            if (t >= 1) {
                #pragma unroll
                for (int i = 0; i < 8; i++) {
                    const int row = 8 * rp + i;
                    ull a0 = pack2(bias, 0.f), a1 = 0, a2 = 0, a3 = 0;
                    const ull* h1p = (const ull*)u.p.h1[row];
                    const ull* h2p = (const ull*)u.p.h2[row];
                    #pragma unroll
                    for (int j = 0; j < 10; j++) {
                        ull v1 = h1p[j], v2 = h2p[j];
                        if (j & 1) { ffma2(a1, v1, wa[j]); ffma2(a3, v2, wb[j]); }
                        else       { ffma2(a0, v1, wa[j]); ffma2(a2, v2, wb[j]); }
                    }
                    float2 s0 = unpack2(a0), s1 = unpack2(a1);
                    float2 s2 = unpack2(a2), s3 = unpack2(a3);
                    u.p.z2[row][g] = ((s0.x + s0.y) + (s1.x + s1.y)) +
                                     ((s2.x + s2.y) + (s3.x + s3.y));
                }
            }
        }
        __syncthreads();

        // ---- phase B: 2 cell updates per thread + x staging ----
        if (isL1) {
            if (t < T_) {
                float zi = u.p.z1[cr][uu],       zf = u.p.z1[cr][H_ + uu];
                float zg = u.p.z1[cr][2*H_ + uu], zo = u.p.z1[cr][3*H_ + uu];
                ca = sigmoidf_(zf) * ca + sigmoidf_(zi) * fmaxf(zg, 0.f);
                u.p.h1[cr][uu] = sigmoidf_(zo) * fmaxf(ca, 0.f);
                zi = u.p.z1[cr][uu + 10];        zf = u.p.z1[cr][H_ + uu + 10];
                zg = u.p.z1[cr][2*H_ + uu + 10]; zo = u.p.z1[cr][3*H_ + uu + 10];
                cb = sigmoidf_(zf) * cb + sigmoidf_(zi) * fmaxf(zg, 0.f);
                u.p.h1[cr][uu + 10] = sigmoidf_(zo) * fmaxf(cb, 0.f);
            }
        } else {
            if (t >= 1) {
                float zi = u.p.z2[cr][uu],       zf = u.p.z2[cr][H_ + uu];
                float zg = u.p.z2[cr][2*H_ + uu], zo = u.p.z2[cr][3*H_ + uu];
                ca = sigmoidf_(zf) * ca + sigmoidf_(zi) * fmaxf(zg, 0.f);
                u.p.h2[cr][uu] = sigmoidf_(zo) * fmaxf(ca, 0.f);
                zi = u.p.z2[cr][uu + 10];        zf = u.p.z2[cr][H_ + uu + 10];
                zg = u.p.z2[cr][2*H_ + uu + 10]; zo = u.p.z2[cr][3*H_ + uu + 10];
                cb = sigmoidf_(zf) * cb + sigmoidf_(zi) * fmaxf(zg, 0.f);
                u.p.h2[cr][uu + 10] = sigmoidf_(zo) * fmaxf(cb, 0.f);
            }
        }
        if (t + 1 < T_) {
            const int tn = (t + 2 < T_) ? t + 2 : T_ - 1;
            u.p.xt[s1row][s1f] = xv1 * sc1 + sh1;       // x(t+1)
            xv1 = px1[(size_t)tn * F_];
            if (has2) {
                u.p.xt[s2row][s2f] = xv2 * sc2 + sh2;
                xv2 = px2[(size_t)tn * F_];
            }
        }
        __syncthreads();
    }

    // dense head: eo[e,b] = h2(T-1) @ dw[e] + db[e]
    if (tid < LROWS) {
        float acc = db[e];
        #pragma unroll
        for (int j = 0; j < H_; j++) acc += u.p.h2[tid][j] * dw[e * H_ + j];
        g_eo[e * B_ + row0 + tid] = acc;
    }
}

// ===========================================================================
// kC: gate (fc1 row @ gate_w, softmax) + combine -> out[b]
// ===========================================================================
__global__ void __launch_bounds__(320) kC_gate_combine(
    const float* __restrict__ GW, const float* __restrict__ GB,
    float* __restrict__ out)
{
    __shared__ float red[10][E_];
    __shared__ float sv[E_];
    __shared__ float ev[E_];
    __shared__ float part[E_];

    const int b = blockIdx.x;
    const int tid = threadIdx.x;
    float acc[E_];
    #pragma unroll
    for (int e = 0; e < E_; e++) acc[e] = 0.f;

    const float* grow = g_fc1 + (size_t)b * D_;
    for (int k = tid; k < D_; k += 320) {
        float gv = grow[k];
        const float4* wp = (const float4*)(GW + (size_t)k * E_);
        float4 w0 = wp[0], w1 = wp[1], w2 = wp[2], w3 = wp[3];
        acc[0]  += gv * w0.x;  acc[1]  += gv * w0.y;
        acc[2]  += gv * w0.z;  acc[3]  += gv * w0.w;
        acc[4]  += gv * w1.x;  acc[5]  += gv * w1.y;
        acc[6]  += gv * w1.z;  acc[7]  += gv * w1.w;
        acc[8]  += gv * w2.x;  acc[9]  += gv * w2.y;
        acc[10] += gv * w2.z;  acc[11] += gv * w2.w;
        acc[12] += gv * w3.x;  acc[13] += gv * w3.y;
        acc[14] += gv * w3.z;  acc[15] += gv * w3.w;
    }
    #pragma unroll
    for (int e = 0; e < E_; e++) {
        #pragma unroll
        for (int off = 16; off > 0; off >>= 1)
            acc[e] += __shfl_down_sync(0xffffffffu, acc[e], off);
    }
    const int warp = tid >> 5, lane = tid & 31;
    if (lane == 0) {
        #pragma unroll
        for (int e = 0; e < E_; e++) red[warp][e] = acc[e];
    }
    __syncthreads();
    if (tid < E_) {
        float s = GB[tid];
        #pragma unroll
        for (int w = 0; w < 10; w++) s += red[w][tid];
        sv[tid] = s;
    }
    __syncthreads();
    if (tid < E_) {
        float m = sv[0];
        #pragma unroll
        for (int e = 1; e < E_; e++) m = fmaxf(m, sv[e]);
        ev[tid] = expf(sv[tid] - m);
    }
    __syncthreads();
    if (tid < E_) {
        float s = 0.f;
        #pragma unroll
        for (int e = 0; e < E_; e++) s += ev[e];
        part[tid] = (ev[tid] / s) * g_eo[tid * B_ + b];
    }
    __syncthreads();
    if (tid == 0) {
        float s = 0.f;
        #pragma unroll
        for (int e = 0; e < E_; e++) s += part[e];
        out[b] = s;
    }
}

// ---------------------------------------------------------------------------
extern "C" void kernel_launch(void* const* d_in, const int* in_sizes, int n_in,
                              void* d_out, int out_size)
{
    const float* x        = (const float*)d_in[0];
    const float* bn_gamma = (const float*)d_in[1];
    const float* bn_beta  = (const float*)d_in[2];
    const float* bn_mean  = (const float*)d_in[3];
    const float* bn_var   = (const float*)d_in[4];
    const float* k1       = (const float*)d_in[5];
    const float* r1       = (const float*)d_in[6];
    const float* b1       = (const float*)d_in[7];
    const float* k2       = (const float*)d_in[8];
    const float* r2       = (const float*)d_in[9];
    const float* b2       = (const float*)d_in[10];
    const float* dw       = (const float*)d_in[11];
    const float* db       = (const float*)d_in[12];
    const float* fc1_w    = (const float*)d_in[13];
    const float* fc1_b    = (const float*)d_in[14];
    const float* gate_w   = (const float*)d_in[15];
    const float* gate_b   = (const float*)d_in[16];
    float* out = (float*)d_out;

    kFat<<<FC1_BLOCKS + LSTM_BLOCKS, 320>>>(
        x, fc1_w, fc1_b, bn_gamma, bn_beta, bn_mean, bn_var,
        k1, r1, b1, k2, r2, b2, dw, db);

    kC_gate_combine<<<B_, 320>>>(gate_w, gate_b, out);
}